// round 4
// baseline (speedup 1.0000x reference)
#include <cuda_runtime.h>
#include <cstdint>

#define BATCH 4
#define NPTS  8192
#define HH    2048
#define WW    2048
#define KOUT  1024
#define RAD   4

typedef unsigned long long ull;

// Persistent scratch (zero-init at load; every launch restores the grid to
// all-zero before finishing -> deterministic graph replays).
__device__ __align__(16) unsigned int g_grid[BATCH * HH * WW]; // 64 MB, float bits
__device__ unsigned int g_pix[BATCH * NPTS];
__device__ ull          g_keys[BATCH * NPTS];

// Compare-exchange keep: keys are globally distinct (low 32 bits = ~idx).
__device__ __forceinline__ ull ce_keep(ull key, ull p, bool keepMax) {
    return (keepMax == (p > key)) ? p : key;
}

// ---------------------------------------------------------------------------
// K1: scatter-max score bits into the per-batch grid; cache pixel ids.
// Positive floats compare identically as unsigned; zero-init grid == 0.0f.
// ---------------------------------------------------------------------------
__global__ void scatter_kernel(const float* __restrict__ lafs,
                               const float* __restrict__ scores) {
    int i = blockIdx.x * blockDim.x + threadIdx.x;
    if (i >= BATCH * NPTS) return;
    const float2* lp = reinterpret_cast<const float2*>(lafs);
    float x = lp[3 * i + 1].x;   // laf[:,0,2]
    float y = lp[3 * i + 2].y;   // laf[:,1,2]
    int xi = (int)rintf(x); xi = min(max(xi, 0), WW - 1);  // rintf == jnp.round (RNE)
    int yi = (int)rintf(y); yi = min(max(yi, 0), HH - 1);
    unsigned p = ((unsigned)(i >> 13) << 22) | ((unsigned)yi << 11) | (unsigned)xi;
    g_pix[i] = p;
    atomicMax(&g_grid[p], __float_as_uint(scores[i]));
}

// ---------------------------------------------------------------------------
// K2 (fused NMS + chunk sort): 32 blocks x 1024 thr. Each thread does the
// 9x9 windowed max for its keypoint, builds the 64-bit key
// (monotone score map << 32 | ~idx), then the block bitonic-sorts its 1024
// keys descending (stages j<=16 via shfl, j>=32 via double-buffered smem,
// 1 barrier/stage) and writes the sorted chunk to g_keys.
// ---------------------------------------------------------------------------
__global__ void __launch_bounds__(1024) nms_sort_kernel(const float* __restrict__ scores) {
    __shared__ ull buf[2][1024];
    int t = threadIdx.x;
    int base = blockIdx.x << 10;
    int i = base + t;

    // --- NMS window ---
    unsigned p = g_pix[i];
    int xi = p & (WW - 1);
    int yi = (p >> 11) & (HH - 1);
    const float* gb = reinterpret_cast<const float*>(g_grid) + (p & 0xFFC00000u);

    float v = __uint_as_float(g_grid[p]);
    float s = scores[i];

    int y0 = max(yi - RAD, 0), y1 = min(yi + RAD, HH - 1);
    int x0 = max(xi - RAD, 0), x1 = min(xi + RAD, WW - 1);
    int q0 = x0 >> 2, q1 = x1 >> 2;

    float wmax = 0.0f;
    for (int yy = y0; yy <= y1; ++yy) {
        const float4* row = reinterpret_cast<const float4*>(gb + yy * WW);
        for (int q = q0; q <= q1; ++q) {
            float4 d = row[q];
            int c = q << 2;
            if (c     >= x0 && c     <= x1) wmax = fmaxf(wmax, d.x);
            if (c + 1 >= x0 && c + 1 <= x1) wmax = fmaxf(wmax, d.y);
            if (c + 2 >= x0 && c + 2 <= x1) wmax = fmaxf(wmax, d.z);
            if (c + 3 >= x0 && c + 3 <= x1) wmax = fmaxf(wmax, d.w);
        }
    }
    bool survive = (s == v) && (wmax <= v);
    unsigned sb = survive ? __float_as_uint(s) : 0xFF800000u;   // -inf if culled
    unsigned m  = (sb & 0x80000000u) ? ~sb : (sb | 0x80000000u);
    ull key = ((ull)m << 32) | (unsigned)(~i);

    // --- in-block bitonic sort, descending ---
    int flip = 0;
    #pragma unroll 1
    for (int k = 2; k <= 1024; k <<= 1) {
        bool desc = (t & k) == 0;
        int j = k >> 1;
        #pragma unroll 1
        for (; j >= 32; j >>= 1) {
            buf[flip][t] = key;
            __syncthreads();
            ull pk = buf[flip][t ^ j];
            flip ^= 1;
            key = ce_keep(key, pk, desc == ((t & j) == 0));
        }
        #pragma unroll 1
        for (; j >= 1; j >>= 1) {
            ull pk = __shfl_xor_sync(0xffffffffu, key, j);
            key = ce_keep(key, pk, desc == ((t & j) == 0));
        }
    }
    g_keys[base + t] = key;
}

// ---------------------------------------------------------------------------
// K3 (full merge tree + epilogue + grid cleanup): 4 blocks (1/batch), 1024
// thr, 64 KB dynamic smem. Level 1: 4 pairwise top-1024 combines held as
// 4 keys/thread, merged concurrently (shared barriers). Level 2: 2 keys.
// Level 3: 1 key. combine(A,B)[i] = max(A[i], B[1023-i]) is the exact
// top-1024 multiset and bitonic -> 10-stage merge re-sorts it.
// ---------------------------------------------------------------------------
__global__ void __launch_bounds__(1024) merge_kernel(const float* __restrict__ lafs,
                                                     float* __restrict__ out) {
    extern __shared__ ull sm[];                // 2 x 4096 keys = 64 KB
    int t = threadIdx.x;
    int b = blockIdx.x;
    const ull* src = g_keys + b * NPTS;

    // grid cleanup (all NMS reads finished at kernel boundary)
    #pragma unroll
    for (int r = 0; r < 8; ++r)
        g_grid[g_pix[b * NPTS + (r << 10) + t]] = 0u;

    // ---- level 1: 4 combines, 4 keys/thread ----
    ull key[4];
    #pragma unroll
    for (int m2 = 0; m2 < 4; ++m2) {
        ull a = src[(m2 << 11) + t];
        ull c = src[(m2 << 11) + 1024 + (1023 - t)];
        key[m2] = (a > c) ? a : c;
    }
    int flip = 0;
    #pragma unroll 1
    for (int j = 512; j >= 32; j >>= 1) {
        #pragma unroll
        for (int m2 = 0; m2 < 4; ++m2) sm[(flip << 12) + (m2 << 10) + t] = key[m2];
        __syncthreads();
        bool keepMax = (t & j) == 0;
        #pragma unroll
        for (int m2 = 0; m2 < 4; ++m2) {
            ull pk = sm[(flip << 12) + (m2 << 10) + (t ^ j)];
            key[m2] = ce_keep(key[m2], pk, keepMax);
        }
        flip ^= 1;
    }
    #pragma unroll
    for (int j = 16; j >= 1; j >>= 1) {
        bool keepMax = (t & j) == 0;
        #pragma unroll
        for (int m2 = 0; m2 < 4; ++m2) {
            ull pk = __shfl_xor_sync(0xffffffffu, key[m2], j);
            key[m2] = ce_keep(key[m2], pk, keepMax);
        }
    }

    // ---- level 2: 2 combines, 2 keys/thread ----
    #pragma unroll
    for (int m2 = 0; m2 < 4; ++m2) sm[(flip << 12) + (m2 << 10) + t] = key[m2];
    __syncthreads();
    {
        ull a = sm[(flip << 12) + t];
        ull c = sm[(flip << 12) + 1024 + (1023 - t)];
        key[0] = (a > c) ? a : c;
        ull d = sm[(flip << 12) + 2048 + t];
        ull e = sm[(flip << 12) + 3072 + (1023 - t)];
        key[1] = (d > e) ? d : e;
    }
    flip ^= 1;
    #pragma unroll 1
    for (int j = 512; j >= 32; j >>= 1) {
        sm[(flip << 12) + t] = key[0];
        sm[(flip << 12) + 1024 + t] = key[1];
        __syncthreads();
        bool keepMax = (t & j) == 0;
        ull p0 = sm[(flip << 12) + (t ^ j)];
        ull p1 = sm[(flip << 12) + 1024 + (t ^ j)];
        key[0] = ce_keep(key[0], p0, keepMax);
        key[1] = ce_keep(key[1], p1, keepMax);
        flip ^= 1;
    }
    #pragma unroll
    for (int j = 16; j >= 1; j >>= 1) {
        bool keepMax = (t & j) == 0;
        ull p0 = __shfl_xor_sync(0xffffffffu, key[0], j);
        ull p1 = __shfl_xor_sync(0xffffffffu, key[1], j);
        key[0] = ce_keep(key[0], p0, keepMax);
        key[1] = ce_keep(key[1], p1, keepMax);
    }

    // ---- level 3: final combine, 1 key/thread ----
    sm[(flip << 12) + t] = key[0];
    sm[(flip << 12) + 1024 + t] = key[1];
    __syncthreads();
    ull fk;
    {
        ull a = sm[(flip << 12) + t];
        ull c = sm[(flip << 12) + 1024 + (1023 - t)];
        fk = (a > c) ? a : c;
    }
    flip ^= 1;
    #pragma unroll 1
    for (int j = 512; j >= 32; j >>= 1) {
        sm[(flip << 12) + t] = fk;
        __syncthreads();
        ull pk = sm[(flip << 12) + (t ^ j)];
        flip ^= 1;
        fk = ce_keep(fk, pk, (t & j) == 0);
    }
    #pragma unroll
    for (int j = 16; j >= 1; j >>= 1) {
        ull pk = __shfl_xor_sync(0xffffffffu, fk, j);
        fk = ce_keep(fk, pk, (t & j) == 0);
    }

    // ---- epilogue: lafs_out [4,1024,2,3] ++ scores_out [4,1024] ----
    {
        int idx = (int)((~(unsigned)fk) & (NPTS - 1));
        unsigned mm = (unsigned)(fk >> 32);
        unsigned sb = (mm & 0x80000000u) ? (mm & 0x7FFFFFFFu) : ~mm;
        float sc = __uint_as_float(sb);

        const float2* srcL = reinterpret_cast<const float2*>(lafs + (size_t)(b * NPTS + idx) * 6);
        float2*       dst  = reinterpret_cast<float2*>(out + (size_t)(b * KOUT + t) * 6);
        dst[0] = srcL[0];
        dst[1] = srcL[1];
        dst[2] = srcL[2];
        out[BATCH * KOUT * 6 + b * KOUT + t] = sc;
    }
}

extern "C" void kernel_launch(void* const* d_in, const int* in_sizes, int n_in,
                              void* d_out, int out_size) {
    const float* lafs   = (const float*)d_in[0];
    const float* scores = (const float*)d_in[1];
    float* out = (float*)d_out;

    cudaFuncSetAttribute(merge_kernel, cudaFuncAttributeMaxDynamicSharedMemorySize, 65536);

    int nthr = BATCH * NPTS;
    scatter_kernel<<<(nthr + 255) / 256, 256>>>(lafs, scores);
    nms_sort_kernel<<<BATCH * 8, 1024>>>(scores);
    merge_kernel<<<BATCH, 1024, 65536>>>(lafs, out);
}

// round 5
// speedup vs baseline: 1.0485x; 1.0485x over previous
#include <cuda_runtime.h>
#include <cstdint>

#define BATCH 4
#define NPTS  8192
#define NTOT  (BATCH * NPTS)     // 32768
#define HH    2048
#define WW    2048
#define KOUT  1024
#define NBLK  128
#define NTHR  256

typedef unsigned long long ull;

// Persistent scratch (zero-init at load; grid restored to zero every launch).
__device__ __align__(16) unsigned int g_grid[BATCH * HH * WW]; // 64 MB, float bits
__device__ unsigned int g_pix[NTOT];
__device__ ull          g_keys[NTOT];
__device__ ull          g_keys2[16 * 1024];
__device__ ull          g_keys3[8 * 1024];

__device__ unsigned g_bar_count;
__device__ volatile unsigned g_bar_gen;

__device__ __forceinline__ void grid_bar() {
    __syncthreads();
    if (threadIdx.x == 0) {
        __threadfence();
        unsigned gen = g_bar_gen;
        if (atomicAdd(&g_bar_count, 1u) == NBLK - 1) {
            g_bar_count = 0;
            __threadfence();
            g_bar_gen = gen + 1;
        } else {
            while (g_bar_gen == gen) { }
        }
        __threadfence();
    }
    __syncthreads();
}

__device__ __forceinline__ ull ce_keep(ull key, ull p, bool keepMax) {
    return (keepMax == (p > key)) ? p : key;
}
// a at lower index, b at higher; descending -> a gets max
__device__ __forceinline__ void ce_pair(ull& a, ull& b, bool desc) {
    ull mx = (a > b) ? a : b;
    ull mn = (a > b) ? b : a;
    a = desc ? mx : mn;
    b = desc ? mn : mx;
}

__shared__ ull smbuf[2][1024];      // 16 KB double buffer

// 10-stage descending bitonic merge of a 1024-element bitonic sequence held as
// key[r] at virtual index e = (r<<8)|tid. 2 register + 3 smem + 5 shfl stages.
__device__ __forceinline__ void merge1024_desc(ull key[4], int tid) {
    ce_pair(key[0], key[2], true);  ce_pair(key[1], key[3], true);   // j=512
    ce_pair(key[0], key[1], true);  ce_pair(key[2], key[3], true);   // j=256
    int flip = 0;
    #pragma unroll
    for (int j = 128; j >= 32; j >>= 1) {
        #pragma unroll
        for (int r = 0; r < 4; ++r) smbuf[flip][(r << 8) | tid] = key[r];
        __syncthreads();
        #pragma unroll
        for (int r = 0; r < 4; ++r) {
            ull pk = smbuf[flip][((r << 8) | tid) ^ j];
            key[r] = ce_keep(key[r], pk, (tid & j) == 0);
        }
        flip ^= 1;
        __syncthreads();
    }
    #pragma unroll
    for (int j = 16; j >= 1; j >>= 1) {
        #pragma unroll
        for (int r = 0; r < 4; ++r) {
            ull pk = __shfl_xor_sync(0xffffffffu, key[r], j);
            key[r] = ce_keep(key[r], pk, (tid & j) == 0);
        }
    }
}

__global__ void __launch_bounds__(NTHR) fused_kernel(const float* __restrict__ lafs,
                                                     const float* __restrict__ scores,
                                                     float* __restrict__ out) {
    int b   = blockIdx.x;
    int tid = threadIdx.x;

    // ---------------- phase 1: scatter-max ----------------
    {
        int i = b * NTHR + tid;                 // 0..32767
        float x = lafs[i * 6 + 2];
        float y = lafs[i * 6 + 5];
        int xi = (int)rintf(x); xi = min(max(xi, 0), WW - 1);   // RNE == jnp.round
        int yi = (int)rintf(y); yi = min(max(yi, 0), HH - 1);
        unsigned p = ((unsigned)(i >> 13) << 22) | ((unsigned)yi << 11) | (unsigned)xi;
        g_pix[i] = p;
        atomicMax(&g_grid[p], __float_as_uint(scores[i]));
    }
    grid_bar();   // bar 1

    // ---------------- phase 2: warp-per-keypoint NMS ----------------
    {
        int w    = b * (NTHR / 32) + (tid >> 5);   // global warp id 0..1023
        int lane = tid & 31;
        int dy = lane / 3 - 4;
        int dq = lane - (lane / 3) * 3;
        bool lane_ok = lane < 27;
        ull keym = 0;
        #pragma unroll 4
        for (int it = 0; it < 32; ++it) {
            int kp = w * 32 + it;
            unsigned p     = g_pix[kp];        // uniform address -> 1 wavefront
            unsigned vbits = g_grid[p];        // pixel max (uniform)
            unsigned sbits = __float_as_uint(scores[kp]);
            int xi = p & (WW - 1);
            int yi = (p >> 11) & (HH - 1);
            const unsigned* gb = g_grid + (p & 0xFFC00000u);
            int x0 = max(xi - 4, 0), x1 = min(xi + 4, WW - 1);
            int q0 = x0 >> 2;
            unsigned mybits = 0;
            if (lane_ok) {
                int yy = yi + dy;
                int qq = min(q0 + dq, (WW >> 2) - 1);
                if (yy >= 0 && yy < HH) {
                    float4 d = *reinterpret_cast<const float4*>(gb + yy * WW + (qq << 2));
                    int c = qq << 2;
                    float m = 0.0f;
                    if (c     >= x0 && c     <= x1) m = fmaxf(m, d.x);
                    if (c + 1 >= x0 && c + 1 <= x1) m = fmaxf(m, d.y);
                    if (c + 2 >= x0 && c + 2 <= x1) m = fmaxf(m, d.z);
                    if (c + 3 >= x0 && c + 3 <= x1) m = fmaxf(m, d.w);
                    mybits = __float_as_uint(m);   // non-negative: uint order == float order
                }
            }
            unsigned wmax = __reduce_max_sync(0xffffffffu, mybits);
            bool survive = (sbits == vbits) && (wmax == vbits);  // wmax >= v always
            unsigned sb = survive ? sbits : 0xFF800000u;         // -inf if culled
            unsigned mk = (sb & 0x80000000u) ? ~sb : (sb | 0x80000000u);
            ull key = ((ull)mk << 32) | (unsigned)(~kp);
            if (it == lane) keym = key;          // park in lane 'it'
        }
        g_keys[w * 32 + lane] = keym;            // one coalesced 256B store/warp
    }
    grid_bar();   // bar 2

    // ---------------- phase 3: chunk sort (blocks 0-31) / grid cleanup (32-127) ----------------
    if (b < 32) {
        int base = b << 10;
        ull key[4];
        #pragma unroll
        for (int r = 0; r < 4; ++r) key[r] = g_keys[base + (r << 8) + tid];

        int flip = 0;
        #pragma unroll 1
        for (int k = 2; k <= 1024; k <<= 1) {
            int j = k >> 1;
            for (; j >= 256; j >>= 1) {           // register stages
                int jr = j >> 8;
                #pragma unroll
                for (int r = 0; r < 4; ++r)
                    if (!(r & jr)) {
                        bool desc = ((((r << 8) | tid) & k) == 0);
                        ce_pair(key[r], key[r | jr], desc);
                    }
            }
            for (; j >= 32; j >>= 1) {            // smem stages (double buffered)
                #pragma unroll
                for (int r = 0; r < 4; ++r) smbuf[flip][(r << 8) | tid] = key[r];
                __syncthreads();
                #pragma unroll
                for (int r = 0; r < 4; ++r) {
                    int e = (r << 8) | tid;
                    bool desc = ((e & k) == 0);
                    ull pk = smbuf[flip][e ^ j];
                    key[r] = ce_keep(key[r], pk, desc == ((e & j) == 0));
                }
                flip ^= 1;
                __syncthreads();
            }
            for (; j >= 1; j >>= 1) {             // shfl stages
                #pragma unroll
                for (int r = 0; r < 4; ++r) {
                    int e = (r << 8) | tid;
                    bool desc = ((e & k) == 0);
                    ull pk = __shfl_xor_sync(0xffffffffu, key[r], j);
                    key[r] = ce_keep(key[r], pk, desc == ((tid & j) == 0));
                }
            }
        }
        #pragma unroll
        for (int r = 0; r < 4; ++r) g_keys[base + (r << 8) + tid] = key[r];
    } else {
        // restore persistent grid to zero (all NMS reads done at bar 2)
        for (int i = (b - 32) * NTHR + tid; i < NTOT; i += 96 * NTHR)
            g_grid[g_pix[i]] = 0u;
    }
    grid_bar();   // bar 3

    // ---------------- phase 4: merge level 1 (16 blocks) ----------------
    if (b < 16) {
        int bb = b >> 2, pair = b & 3;
        const ull* A = g_keys + bb * NPTS + pair * 2048;
        ull key[4];
        #pragma unroll
        for (int r = 0; r < 4; ++r) {
            int e = (r << 8) | tid;
            ull a = A[e];
            ull c = A[1024 + (1023 - e)];
            key[r] = (a > c) ? a : c;             // exact top-1024 multiset, bitonic
        }
        merge1024_desc(key, tid);
        #pragma unroll
        for (int r = 0; r < 4; ++r) g_keys2[(bb * 4 + pair) * 1024 + ((r << 8) | tid)] = key[r];
    }
    grid_bar();   // bar 4

    // ---------------- phase 5: merge level 2 (8 blocks) ----------------
    if (b < 8) {
        int bb = b >> 1, pair = b & 1;
        const ull* A = g_keys2 + bb * 4096 + pair * 2048;
        ull key[4];
        #pragma unroll
        for (int r = 0; r < 4; ++r) {
            int e = (r << 8) | tid;
            ull a = A[e];
            ull c = A[1024 + (1023 - e)];
            key[r] = (a > c) ? a : c;
        }
        merge1024_desc(key, tid);
        #pragma unroll
        for (int r = 0; r < 4; ++r) g_keys3[(bb * 2 + pair) * 1024 + ((r << 8) | tid)] = key[r];
    }
    grid_bar();   // bar 5

    // ---------------- phase 6: merge level 3 + epilogue (4 blocks) ----------------
    if (b < 4) {
        const ull* A = g_keys3 + b * 2048;
        ull key[4];
        #pragma unroll
        for (int r = 0; r < 4; ++r) {
            int e = (r << 8) | tid;
            ull a = A[e];
            ull c = A[1024 + (1023 - e)];
            key[r] = (a > c) ? a : c;
        }
        merge1024_desc(key, tid);

        // outputs: lafs_out [4,1024,2,3] ++ scores_out [4,1024]
        #pragma unroll
        for (int r = 0; r < 4; ++r) {
            int e = (r << 8) | tid;
            ull kk = key[r];
            int idx = (int)((~(unsigned)kk) & (NPTS - 1));
            unsigned mm = (unsigned)(kk >> 32);
            unsigned sb = (mm & 0x80000000u) ? (mm & 0x7FFFFFFFu) : ~mm;
            float sc = __uint_as_float(sb);

            const float2* srcL = reinterpret_cast<const float2*>(lafs + (size_t)(b * NPTS + idx) * 6);
            float2*       dst  = reinterpret_cast<float2*>(out + (size_t)(b * KOUT + e) * 6);
            dst[0] = srcL[0];
            dst[1] = srcL[1];
            dst[2] = srcL[2];
            out[BATCH * KOUT * 6 + b * KOUT + e] = sc;
        }
    }
}

extern "C" void kernel_launch(void* const* d_in, const int* in_sizes, int n_in,
                              void* d_out, int out_size) {
    const float* lafs   = (const float*)d_in[0];
    const float* scores = (const float*)d_in[1];
    float* out = (float*)d_out;
    fused_kernel<<<NBLK, NTHR>>>(lafs, scores, out);
}

// round 6
// speedup vs baseline: 1.3198x; 1.2587x over previous
#include <cuda_runtime.h>
#include <cstdint>

#define BATCH 4
#define NPTS  8192
#define NTOT  (BATCH * NPTS)     // 32768
#define HH    2048
#define WW    2048
#define KOUT  1024
#define RAD   4

typedef unsigned long long ull;

// Persistent scratch (zero-init at load; grid restored to zero every launch).
__device__ __align__(16) unsigned int g_grid[BATCH * HH * WW]; // 64 MB, float bits
__device__ unsigned int g_pix[NTOT];
__device__ ull          g_keys[NTOT];
__device__ ull          g_keys2[16 * 1024];
__device__ ull          g_keys3[8 * 1024];

__device__ unsigned g_bar_count;
__device__ volatile unsigned g_bar_gen;

template <int NB>
__device__ __forceinline__ void grid_bar() {
    __syncthreads();
    if (threadIdx.x == 0) {
        __threadfence();
        unsigned gen = g_bar_gen;
        if (atomicAdd(&g_bar_count, 1u) == NB - 1) {
            g_bar_count = 0;
            __threadfence();
            g_bar_gen = gen + 1;
        } else {
            while (g_bar_gen == gen) { }
        }
        __threadfence();
    }
    __syncthreads();
}

__device__ __forceinline__ ull ce_keep(ull key, ull p, bool keepMax) {
    return (keepMax == (p > key)) ? p : key;
}

// ---------------------------------------------------------------------------
// K_A: scatter-max -> grid barrier -> thread-per-keypoint 9x9 NMS -> keys.
// 128 blocks x 256 threads (all co-resident on 148 SMs).
// ---------------------------------------------------------------------------
__global__ void __launch_bounds__(256) scatter_nms_kernel(const float* __restrict__ lafs,
                                                          const float* __restrict__ scores) {
    int i = blockIdx.x * 256 + threadIdx.x;    // 0..32767, one keypoint

    // --- phase 1: scatter-max score bits; positive floats order as uints ---
    float x = lafs[i * 6 + 2];   // laf[:,0,2]
    float y = lafs[i * 6 + 5];   // laf[:,1,2]
    int xi = (int)rintf(x); xi = min(max(xi, 0), WW - 1);  // rintf == jnp.round (RNE)
    int yi = (int)rintf(y); yi = min(max(yi, 0), HH - 1);
    unsigned p = ((unsigned)(i >> 13) << 22) | ((unsigned)yi << 11) | (unsigned)xi;
    g_pix[i] = p;
    float s = scores[i];
    atomicMax(&g_grid[p], __float_as_uint(s));

    grid_bar<128>();

    // --- phase 2: 9x9 windowed max read from the sparse grid ---
    const float* gb = reinterpret_cast<const float*>(g_grid) + (p & 0xFFC00000u);
    float v = __uint_as_float(g_grid[p]);

    int y0 = max(yi - RAD, 0), y1 = min(yi + RAD, HH - 1);
    int x0 = max(xi - RAD, 0), x1 = min(xi + RAD, WW - 1);
    int q0 = x0 >> 2, q1 = x1 >> 2;

    float wmax = 0.0f;
    for (int yy = y0; yy <= y1; ++yy) {
        const float4* row = reinterpret_cast<const float4*>(gb + yy * WW);
        for (int q = q0; q <= q1; ++q) {
            float4 d = row[q];
            int c = q << 2;
            if (c     >= x0 && c     <= x1) wmax = fmaxf(wmax, d.x);
            if (c + 1 >= x0 && c + 1 <= x1) wmax = fmaxf(wmax, d.y);
            if (c + 2 >= x0 && c + 2 <= x1) wmax = fmaxf(wmax, d.z);
            if (c + 3 >= x0 && c + 3 <= x1) wmax = fmaxf(wmax, d.w);
        }
    }
    bool survive = (s == v) && (wmax <= v);    // wmax >= v always (window holds center)
    unsigned sb = survive ? __float_as_uint(s) : 0xFF800000u;   // -inf if culled
    unsigned m  = (sb & 0x80000000u) ? ~sb : (sb | 0x80000000u);
    g_keys[i] = ((ull)m << 32) | (unsigned)(~i);
}

// ---------------------------------------------------------------------------
// K_B: 32 blocks x 1024 threads, persistent with 32-block grid barrier.
// Phase A: grid cleanup (1 px/thread) + bitonic sort of own 1024-key chunk
//          (j<=16 shfl, j>=32 double-buffered smem, 1 barrier/stage).
// Phase B/C/D: merge tree. combine(A,B)[i] = max(A[i], B[1023-i]) is the
// exact top-1024 multiset and bitonic -> 10-stage merge re-sorts it.
// ---------------------------------------------------------------------------
__global__ void __launch_bounds__(1024) sortmerge_kernel(const float* __restrict__ lafs,
                                                         float* __restrict__ out) {
    __shared__ ull buf[2][1024];
    int t = threadIdx.x;
    int b = blockIdx.x;

    // cleanup: restore persistent grid to zero (all NMS reads done at boundary)
    g_grid[g_pix[(b << 10) + t]] = 0u;

    // ---- sort own chunk, descending ----
    ull key = g_keys[(b << 10) + t];
    int flip = 0;
    #pragma unroll 1
    for (int k = 2; k <= 1024; k <<= 1) {
        bool desc = (t & k) == 0;
        int j = k >> 1;
        #pragma unroll 1
        for (; j >= 32; j >>= 1) {
            buf[flip][t] = key;
            __syncthreads();
            ull pk = buf[flip][t ^ j];
            flip ^= 1;
            key = ce_keep(key, pk, desc == ((t & j) == 0));
        }
        #pragma unroll 1
        for (; j >= 1; j >>= 1) {
            ull pk = __shfl_xor_sync(0xffffffffu, key, j);
            key = ce_keep(key, pk, desc == ((t & j) == 0));
        }
    }
    g_keys[(b << 10) + t] = key;

    grid_bar<32>();

    // ---- merge level 1: 16 blocks, pair (2m, 2m+1) -> g_keys2 ----
    if (b < 16) {
        int bb = b >> 2, m = b & 3;
        const ull* src = g_keys + (bb << 13) + (m << 11);
        ull a = src[t];
        ull c = src[1024 + (1023 - t)];
        ull kk = (a > c) ? a : c;
        int fl = 0;
        #pragma unroll 1
        for (int j = 512; j >= 32; j >>= 1) {
            buf[fl][t] = kk;
            __syncthreads();
            ull pk = buf[fl][t ^ j];
            fl ^= 1;
            kk = ce_keep(kk, pk, (t & j) == 0);
        }
        #pragma unroll
        for (int j = 16; j >= 1; j >>= 1) {
            ull pk = __shfl_xor_sync(0xffffffffu, kk, j);
            kk = ce_keep(kk, pk, (t & j) == 0);
        }
        g_keys2[b * 1024 + t] = kk;
    }
    grid_bar<32>();

    // ---- merge level 2: 8 blocks -> g_keys3 ----
    if (b < 8) {
        const ull* src = g_keys2 + b * 2048;
        ull a = src[t];
        ull c = src[1024 + (1023 - t)];
        ull kk = (a > c) ? a : c;
        int fl = 0;
        #pragma unroll 1
        for (int j = 512; j >= 32; j >>= 1) {
            buf[fl][t] = kk;
            __syncthreads();
            ull pk = buf[fl][t ^ j];
            fl ^= 1;
            kk = ce_keep(kk, pk, (t & j) == 0);
        }
        #pragma unroll
        for (int j = 16; j >= 1; j >>= 1) {
            ull pk = __shfl_xor_sync(0xffffffffu, kk, j);
            kk = ce_keep(kk, pk, (t & j) == 0);
        }
        g_keys3[b * 1024 + t] = kk;
    }
    grid_bar<32>();

    // ---- merge level 3 + epilogue: 4 blocks (1 per batch) ----
    if (b < 4) {
        const ull* src = g_keys3 + b * 2048;
        ull a = src[t];
        ull c = src[1024 + (1023 - t)];
        ull kk = (a > c) ? a : c;
        int fl = 0;
        #pragma unroll 1
        for (int j = 512; j >= 32; j >>= 1) {
            buf[fl][t] = kk;
            __syncthreads();
            ull pk = buf[fl][t ^ j];
            fl ^= 1;
            kk = ce_keep(kk, pk, (t & j) == 0);
        }
        #pragma unroll
        for (int j = 16; j >= 1; j >>= 1) {
            ull pk = __shfl_xor_sync(0xffffffffu, kk, j);
            kk = ce_keep(kk, pk, (t & j) == 0);
        }

        // outputs: lafs_out [4,1024,2,3] ++ scores_out [4,1024]
        int idx = (int)((~(unsigned)kk) & (NPTS - 1));
        unsigned mm = (unsigned)(kk >> 32);
        unsigned sb = (mm & 0x80000000u) ? (mm & 0x7FFFFFFFu) : ~mm;
        float sc = __uint_as_float(sb);

        const float2* srcL = reinterpret_cast<const float2*>(lafs + (size_t)(b * NPTS + idx) * 6);
        float2*       dst  = reinterpret_cast<float2*>(out + (size_t)(b * KOUT + t) * 6);
        dst[0] = srcL[0];
        dst[1] = srcL[1];
        dst[2] = srcL[2];
        out[BATCH * KOUT * 6 + b * KOUT + t] = sc;
    }
}

extern "C" void kernel_launch(void* const* d_in, const int* in_sizes, int n_in,
                              void* d_out, int out_size) {
    const float* lafs   = (const float*)d_in[0];
    const float* scores = (const float*)d_in[1];
    float* out = (float*)d_out;

    scatter_nms_kernel<<<128, 256>>>(lafs, scores);
    sortmerge_kernel<<<32, 1024>>>(lafs, out);
}

// round 7
// speedup vs baseline: 1.4056x; 1.0650x over previous
#include <cuda_runtime.h>
#include <cstdint>

#define BATCH 4
#define NPTS  8192
#define NTOT  (BATCH * NPTS)     // 32768
#define HH    2048
#define WW    2048
#define KOUT  1024
#define RAD   4

typedef unsigned long long ull;

// Persistent scratch (zero-init at load; grid restored to zero every launch).
__device__ __align__(16) unsigned int g_grid[BATCH * HH * WW]; // 64 MB, float bits
__device__ unsigned int g_pix[NTOT];
__device__ ull          g_keys[NTOT];

__device__ unsigned g_bar_count;
__device__ volatile unsigned g_bar_gen;

template <int NB>
__device__ __forceinline__ void grid_bar() {
    __syncthreads();
    if (threadIdx.x == 0) {
        __threadfence();
        unsigned gen = g_bar_gen;
        if (atomicAdd(&g_bar_count, 1u) == NB - 1) {
            g_bar_count = 0;
            __threadfence();
            g_bar_gen = gen + 1;
        } else {
            while (g_bar_gen == gen) { }
        }
        __threadfence();
    }
    __syncthreads();
}

__device__ __forceinline__ ull ce_keep(ull key, ull p, bool keepMax) {
    return (keepMax == (p > key)) ? p : key;
}

// ---------------------------------------------------------------------------
// K_A: scatter-max -> grid barrier -> thread-per-keypoint 9x9 NMS -> keys.
// 128 blocks x 256 threads (co-resident; NMS needs this wide shape for
// L1tex wavefront spreading — measured in R4/R5).
// ---------------------------------------------------------------------------
__global__ void __launch_bounds__(256) scatter_nms_kernel(const float* __restrict__ lafs,
                                                          const float* __restrict__ scores) {
    int i = blockIdx.x * 256 + threadIdx.x;    // one keypoint

    // --- phase 1: scatter-max score bits (positive floats order as uints) ---
    float x = lafs[i * 6 + 2];   // laf[:,0,2]
    float y = lafs[i * 6 + 5];   // laf[:,1,2]
    int xi = (int)rintf(x); xi = min(max(xi, 0), WW - 1);  // rintf == jnp.round (RNE)
    int yi = (int)rintf(y); yi = min(max(yi, 0), HH - 1);
    unsigned p = ((unsigned)(i >> 13) << 22) | ((unsigned)yi << 11) | (unsigned)xi;
    g_pix[i] = p;
    float s = scores[i];
    atomicMax(&g_grid[p], __float_as_uint(s));

    grid_bar<128>();

    // --- phase 2: 9x9 windowed max read from the sparse grid ---
    const float* gb = reinterpret_cast<const float*>(g_grid) + (p & 0xFFC00000u);
    float v = __uint_as_float(g_grid[p]);

    int y0 = max(yi - RAD, 0), y1 = min(yi + RAD, HH - 1);
    int x0 = max(xi - RAD, 0), x1 = min(xi + RAD, WW - 1);
    int q0 = x0 >> 2, q1 = x1 >> 2;

    float wmax = 0.0f;
    for (int yy = y0; yy <= y1; ++yy) {
        const float4* row = reinterpret_cast<const float4*>(gb + yy * WW);
        for (int q = q0; q <= q1; ++q) {
            float4 d = row[q];
            int c = q << 2;
            if (c     >= x0 && c     <= x1) wmax = fmaxf(wmax, d.x);
            if (c + 1 >= x0 && c + 1 <= x1) wmax = fmaxf(wmax, d.y);
            if (c + 2 >= x0 && c + 2 <= x1) wmax = fmaxf(wmax, d.z);
            if (c + 3 >= x0 && c + 3 <= x1) wmax = fmaxf(wmax, d.w);
        }
    }
    bool survive = (s == v) && (wmax <= v);    // wmax >= v always (window holds center)
    unsigned sb = survive ? __float_as_uint(s) : 0xFF800000u;   // -inf if culled
    unsigned m  = (sb & 0x80000000u) ? ~sb : (sb | 0x80000000u);
    g_keys[i] = ((ull)m << 32) | (unsigned)(~i);
}

// ---------------------------------------------------------------------------
// K_B: 32 blocks x 1024 threads, 64 KB dynamic smem.
// Phase A (all 32): grid cleanup (1 px/thr) + bitonic sort own 1024-key chunk.
// ONE grid barrier. Then blocks 4-31 exit; blocks 0-3 each run the complete
// 3-level merge tree for their batch using only block-level syncs.
// combine(A,B)[i] = max(A[i], B[1023-i]) = exact top-1024 multiset, bitonic.
// ---------------------------------------------------------------------------
__global__ void __launch_bounds__(1024) sortmerge_kernel(const float* __restrict__ lafs,
                                                         float* __restrict__ out) {
    extern __shared__ ull sm[];            // 8192 ull = 64 KB (double buffer 2x4096)
    int t = threadIdx.x;
    int b = blockIdx.x;

    // cleanup: restore persistent grid to zero (all NMS reads done at boundary)
    g_grid[g_pix[(b << 10) + t]] = 0u;

    // ---- sort own chunk, descending (j<=16 shfl, j>=32 double-buffered smem) ----
    ull key = g_keys[(b << 10) + t];
    {
        int flip = 0;
        #pragma unroll 1
        for (int k = 2; k <= 1024; k <<= 1) {
            bool desc = (t & k) == 0;
            int j = k >> 1;
            #pragma unroll 1
            for (; j >= 32; j >>= 1) {
                sm[(flip << 10) + t] = key;
                __syncthreads();
                ull pk = sm[(flip << 10) + (t ^ j)];
                flip ^= 1;
                key = ce_keep(key, pk, desc == ((t & j) == 0));
            }
            #pragma unroll 1
            for (; j >= 1; j >>= 1) {
                ull pk = __shfl_xor_sync(0xffffffffu, key, j);
                key = ce_keep(key, pk, desc == ((t & j) == 0));
            }
        }
    }
    g_keys[(b << 10) + t] = key;

    grid_bar<32>();
    if (b >= 4) return;                    // non-merging blocks done

    __syncthreads();                       // smem reuse boundary after sort

    // ---- full merge tree for batch b, in-block ----
    const ull* src = g_keys + (b << 13);

    // level 1: 4 combines, lists held as key4[m] = element t of list m
    ull key4[4];
    #pragma unroll
    for (int m = 0; m < 4; ++m) {
        ull a = src[(m << 11) + t];
        ull c = src[(m << 11) + 1024 + (1023 - t)];
        key4[m] = (a > c) ? a : c;
    }
    int flip = 0;
    #pragma unroll 1
    for (int j = 512; j >= 32; j >>= 1) {
        #pragma unroll
        for (int m = 0; m < 4; ++m) sm[(flip << 12) + (m << 10) + t] = key4[m];
        __syncthreads();
        bool keepMax = (t & j) == 0;
        #pragma unroll
        for (int m = 0; m < 4; ++m) {
            ull pk = sm[(flip << 12) + (m << 10) + (t ^ j)];
            key4[m] = ce_keep(key4[m], pk, keepMax);
        }
        flip ^= 1;
    }
    #pragma unroll
    for (int j = 16; j >= 1; j >>= 1) {
        bool keepMax = (t & j) == 0;
        #pragma unroll
        for (int m = 0; m < 4; ++m) {
            ull pk = __shfl_xor_sync(0xffffffffu, key4[m], j);
            key4[m] = ce_keep(key4[m], pk, keepMax);
        }
    }

    // level 2: 2 combines (needs cross-thread data -> via smem)
    #pragma unroll
    for (int m = 0; m < 4; ++m) sm[(flip << 12) + (m << 10) + t] = key4[m];
    __syncthreads();
    ull k0, k1;
    {
        const ull* L = sm + (flip << 12);
        ull a = L[t],        c = L[1024 + (1023 - t)];
        k0 = (a > c) ? a : c;
        ull d = L[2048 + t], e = L[3072 + (1023 - t)];
        k1 = (d > e) ? d : e;
    }
    flip ^= 1;
    #pragma unroll 1
    for (int j = 512; j >= 32; j >>= 1) {
        sm[(flip << 12) + t] = k0;
        sm[(flip << 12) + 1024 + t] = k1;
        __syncthreads();
        bool keepMax = (t & j) == 0;
        ull p0 = sm[(flip << 12) + (t ^ j)];
        ull p1 = sm[(flip << 12) + 1024 + (t ^ j)];
        k0 = ce_keep(k0, p0, keepMax);
        k1 = ce_keep(k1, p1, keepMax);
        flip ^= 1;
    }
    #pragma unroll
    for (int j = 16; j >= 1; j >>= 1) {
        bool keepMax = (t & j) == 0;
        ull p0 = __shfl_xor_sync(0xffffffffu, k0, j);
        ull p1 = __shfl_xor_sync(0xffffffffu, k1, j);
        k0 = ce_keep(k0, p0, keepMax);
        k1 = ce_keep(k1, p1, keepMax);
    }

    // level 3: final combine
    sm[(flip << 12) + t] = k0;
    sm[(flip << 12) + 1024 + t] = k1;
    __syncthreads();
    ull fk;
    {
        const ull* L = sm + (flip << 12);
        ull a = L[t];
        ull c = L[1024 + (1023 - t)];
        fk = (a > c) ? a : c;
    }
    flip ^= 1;
    #pragma unroll 1
    for (int j = 512; j >= 32; j >>= 1) {
        sm[(flip << 12) + t] = fk;
        __syncthreads();
        ull pk = sm[(flip << 12) + (t ^ j)];
        flip ^= 1;
        fk = ce_keep(fk, pk, (t & j) == 0);
    }
    #pragma unroll
    for (int j = 16; j >= 1; j >>= 1) {
        ull pk = __shfl_xor_sync(0xffffffffu, fk, j);
        fk = ce_keep(fk, pk, (t & j) == 0);
    }

    // ---- epilogue: lafs_out [4,1024,2,3] ++ scores_out [4,1024] ----
    {
        int idx = (int)((~(unsigned)fk) & (NPTS - 1));
        unsigned mm = (unsigned)(fk >> 32);
        unsigned sb = (mm & 0x80000000u) ? (mm & 0x7FFFFFFFu) : ~mm;
        float sc = __uint_as_float(sb);

        const float2* srcL = reinterpret_cast<const float2*>(lafs + (size_t)((b << 13) + idx) * 6);
        float2*       dst  = reinterpret_cast<float2*>(out + (size_t)(b * KOUT + t) * 6);
        dst[0] = srcL[0];
        dst[1] = srcL[1];
        dst[2] = srcL[2];
        out[BATCH * KOUT * 6 + b * KOUT + t] = sc;
    }
}

extern "C" void kernel_launch(void* const* d_in, const int* in_sizes, int n_in,
                              void* d_out, int out_size) {
    const float* lafs   = (const float*)d_in[0];
    const float* scores = (const float*)d_in[1];
    float* out = (float*)d_out;

    cudaFuncSetAttribute(sortmerge_kernel, cudaFuncAttributeMaxDynamicSharedMemorySize, 65536);

    scatter_nms_kernel<<<128, 256>>>(lafs, scores);
    sortmerge_kernel<<<32, 1024, 65536>>>(lafs, out);
}

// round 8
// speedup vs baseline: 1.4173x; 1.0083x over previous
#include <cuda_runtime.h>
#include <cstdint>

#define BATCH 4
#define NPTS  8192
#define NTOT  (BATCH * NPTS)     // 32768
#define HH    2048
#define WW    2048
#define KOUT  1024
#define RAD   4

typedef unsigned long long ull;

// Persistent scratch (zero-init at load; grid restored to zero every launch).
__device__ __align__(16) unsigned int g_grid[BATCH * HH * WW]; // 64 MB, float bits
__device__ unsigned int g_pix[NTOT];
__device__ ull          g_keys[NTOT];

__device__ unsigned g_barA_count[BATCH];
__device__ volatile unsigned g_barA_gen[BATCH];
__device__ unsigned g_done[BATCH];          // chunks-sorted counter, reset in K_A

// 32-block per-batch barrier (blocks 32b .. 32b+31 of K_A).
__device__ __forceinline__ void batch_bar(int c) {
    __syncthreads();
    if (threadIdx.x == 0) {
        __threadfence();
        unsigned gen = g_barA_gen[c];
        if (atomicAdd(&g_barA_count[c], 1u) == 31u) {
            g_barA_count[c] = 0;
            __threadfence();
            g_barA_gen[c] = gen + 1;
        } else {
            while (g_barA_gen[c] == gen) { }
        }
        __threadfence();
    }
    __syncthreads();
}

__device__ __forceinline__ ull ce_keep(ull key, ull p, bool keepMax) {
    return (keepMax == (p > key)) ? p : key;
}

// ---------------------------------------------------------------------------
// K_A: scatter-max -> per-batch barrier -> thread-per-keypoint 9x9 NMS.
// 128 blocks x 256 threads; blocks 32b..32b+31 own batch b (i>>13 == b).
// ---------------------------------------------------------------------------
__global__ void __launch_bounds__(256) scatter_nms_kernel(const float* __restrict__ lafs,
                                                          const float* __restrict__ scores) {
    int i = blockIdx.x * 256 + threadIdx.x;    // one keypoint
    int batch = i >> 13;

    if (blockIdx.x == 0 && threadIdx.x < BATCH) g_done[threadIdx.x] = 0;  // reset for K_B

    // --- phase 1: scatter-max score bits (positive floats order as uints) ---
    float x = lafs[i * 6 + 2];   // laf[:,0,2]
    float y = lafs[i * 6 + 5];   // laf[:,1,2]
    int xi = (int)rintf(x); xi = min(max(xi, 0), WW - 1);  // rintf == jnp.round (RNE)
    int yi = (int)rintf(y); yi = min(max(yi, 0), HH - 1);
    unsigned p = ((unsigned)batch << 22) | ((unsigned)yi << 11) | (unsigned)xi;
    g_pix[i] = p;
    float s = scores[i];
    atomicMax(&g_grid[p], __float_as_uint(s));

    batch_bar(batch);   // only this batch's scatters must be done (windows stay in-batch)

    // --- phase 2: 9x9 windowed max read from the sparse grid ---
    const float* gb = reinterpret_cast<const float*>(g_grid) + (p & 0xFFC00000u);
    float v = __uint_as_float(g_grid[p]);

    int y0 = max(yi - RAD, 0), y1 = min(yi + RAD, HH - 1);
    int x0 = max(xi - RAD, 0), x1 = min(xi + RAD, WW - 1);
    int q0 = x0 >> 2, q1 = x1 >> 2;

    float wmax = 0.0f;
    for (int yy = y0; yy <= y1; ++yy) {
        const float4* row = reinterpret_cast<const float4*>(gb + yy * WW);
        for (int q = q0; q <= q1; ++q) {
            float4 d = row[q];
            int c = q << 2;
            if (c     >= x0 && c     <= x1) wmax = fmaxf(wmax, d.x);
            if (c + 1 >= x0 && c + 1 <= x1) wmax = fmaxf(wmax, d.y);
            if (c + 2 >= x0 && c + 2 <= x1) wmax = fmaxf(wmax, d.z);
            if (c + 3 >= x0 && c + 3 <= x1) wmax = fmaxf(wmax, d.w);
        }
    }
    bool survive = (s == v) && (wmax <= v);    // wmax >= v always (window holds center)
    unsigned sb = survive ? __float_as_uint(s) : 0xFF800000u;   // -inf if culled
    unsigned m  = (sb & 0x80000000u) ? ~sb : (sb | 0x80000000u);
    g_keys[i] = ((ull)m << 32) | (unsigned)(~i);
}

// ---------------------------------------------------------------------------
// K_B: 32 blocks x 1024 threads, 64 KB dynamic smem.
// Every block: grid cleanup (1 px/thr, fire-and-forget) + bitonic sort of its
// own 1024-key chunk + signal g_done[batch]. Blocks with (b&7)!=0 then exit.
// Blocks 8bb spin on g_done[bb]==8 and run the full 3-level merge tree for
// batch bb in-block (combine(A,B)[i] = max(A[i], B[1023-i]) = exact top-1024
// multiset, bitonic -> 10-stage merge), then write outputs.
// ---------------------------------------------------------------------------
__global__ void __launch_bounds__(1024) sortmerge_kernel(const float* __restrict__ lafs,
                                                         float* __restrict__ out) {
    extern __shared__ ull sm[];            // double buffer 2 x 4096 ull = 64 KB
    int t = threadIdx.x;
    int b = blockIdx.x;
    int bb = b >> 3;                       // batch

    // cleanup: restore persistent grid (all NMS reads done at kernel boundary)
    g_grid[g_pix[(b << 10) + t]] = 0u;

    // ---- sort own chunk, descending (j<=16 shfl, j>=32 double-buffered smem) ----
    ull key = g_keys[(b << 10) + t];
    {
        int flip = 0;
        #pragma unroll 1
        for (int k = 2; k <= 1024; k <<= 1) {
            bool desc = (t & k) == 0;
            int j = k >> 1;
            #pragma unroll 1
            for (; j >= 32; j >>= 1) {
                sm[(flip << 10) + t] = key;
                __syncthreads();
                ull pk = sm[(flip << 10) + (t ^ j)];
                flip ^= 1;
                key = ce_keep(key, pk, desc == ((t & j) == 0));
            }
            #pragma unroll 1
            for (; j >= 1; j >>= 1) {
                ull pk = __shfl_xor_sync(0xffffffffu, key, j);
                key = ce_keep(key, pk, desc == ((t & j) == 0));
            }
        }
    }
    g_keys[(b << 10) + t] = key;

    // signal chunk done (cumulative fence via syncthreads + tid0 fence)
    __syncthreads();
    if (t == 0) {
        __threadfence();
        atomicAdd(&g_done[bb], 1u);
    }
    if (b & 7) return;                     // non-merge blocks done

    // merge block: wait for own batch's 8 chunks
    if (t == 0) {
        while (((volatile unsigned*)g_done)[bb] < 8u) { }
        __threadfence();
    }
    __syncthreads();

    // ---- full merge tree for batch bb, in-block ----
    const ull* src = g_keys + (bb << 13);

    // level 1: 4 combines, key4[m] = element t of merged list m
    ull key4[4];
    #pragma unroll
    for (int m = 0; m < 4; ++m) {
        ull a = src[(m << 11) + t];
        ull c = src[(m << 11) + 1024 + (1023 - t)];
        key4[m] = (a > c) ? a : c;
    }
    int flip = 0;
    #pragma unroll 1
    for (int j = 512; j >= 32; j >>= 1) {
        #pragma unroll
        for (int m = 0; m < 4; ++m) sm[(flip << 12) + (m << 10) + t] = key4[m];
        __syncthreads();
        bool keepMax = (t & j) == 0;
        #pragma unroll
        for (int m = 0; m < 4; ++m) {
            ull pk = sm[(flip << 12) + (m << 10) + (t ^ j)];
            key4[m] = ce_keep(key4[m], pk, keepMax);
        }
        flip ^= 1;
    }
    #pragma unroll
    for (int j = 16; j >= 1; j >>= 1) {
        bool keepMax = (t & j) == 0;
        #pragma unroll
        for (int m = 0; m < 4; ++m) {
            ull pk = __shfl_xor_sync(0xffffffffu, key4[m], j);
            key4[m] = ce_keep(key4[m], pk, keepMax);
        }
    }

    // level 2: 2 combines (cross-thread data via smem)
    #pragma unroll
    for (int m = 0; m < 4; ++m) sm[(flip << 12) + (m << 10) + t] = key4[m];
    __syncthreads();
    ull k0, k1;
    {
        const ull* L = sm + (flip << 12);
        ull a = L[t],        c = L[1024 + (1023 - t)];
        k0 = (a > c) ? a : c;
        ull d = L[2048 + t], e = L[3072 + (1023 - t)];
        k1 = (d > e) ? d : e;
    }
    flip ^= 1;
    #pragma unroll 1
    for (int j = 512; j >= 32; j >>= 1) {
        sm[(flip << 12) + t] = k0;
        sm[(flip << 12) + 1024 + t] = k1;
        __syncthreads();
        bool keepMax = (t & j) == 0;
        ull p0 = sm[(flip << 12) + (t ^ j)];
        ull p1 = sm[(flip << 12) + 1024 + (t ^ j)];
        k0 = ce_keep(k0, p0, keepMax);
        k1 = ce_keep(k1, p1, keepMax);
        flip ^= 1;
    }
    #pragma unroll
    for (int j = 16; j >= 1; j >>= 1) {
        bool keepMax = (t & j) == 0;
        ull p0 = __shfl_xor_sync(0xffffffffu, k0, j);
        ull p1 = __shfl_xor_sync(0xffffffffu, k1, j);
        k0 = ce_keep(k0, p0, keepMax);
        k1 = ce_keep(k1, p1, keepMax);
    }

    // level 3: final combine
    sm[(flip << 12) + t] = k0;
    sm[(flip << 12) + 1024 + t] = k1;
    __syncthreads();
    ull fk;
    {
        const ull* L = sm + (flip << 12);
        ull a = L[t];
        ull c = L[1024 + (1023 - t)];
        fk = (a > c) ? a : c;
    }
    flip ^= 1;
    #pragma unroll 1
    for (int j = 512; j >= 32; j >>= 1) {
        sm[(flip << 12) + t] = fk;
        __syncthreads();
        ull pk = sm[(flip << 12) + (t ^ j)];
        flip ^= 1;
        fk = ce_keep(fk, pk, (t & j) == 0);
    }
    #pragma unroll
    for (int j = 16; j >= 1; j >>= 1) {
        ull pk = __shfl_xor_sync(0xffffffffu, fk, j);
        fk = ce_keep(fk, pk, (t & j) == 0);
    }

    // ---- epilogue: lafs_out [4,1024,2,3] ++ scores_out [4,1024] ----
    {
        int idx = (int)((~(unsigned)fk) & (NPTS - 1));
        unsigned mm = (unsigned)(fk >> 32);
        unsigned sb = (mm & 0x80000000u) ? (mm & 0x7FFFFFFFu) : ~mm;
        float sc = __uint_as_float(sb);

        const float2* srcL = reinterpret_cast<const float2*>(lafs + (size_t)((bb << 13) + idx) * 6);
        float2*       dst  = reinterpret_cast<float2*>(out + (size_t)(bb * KOUT + t) * 6);
        dst[0] = srcL[0];
        dst[1] = srcL[1];
        dst[2] = srcL[2];
        out[BATCH * KOUT * 6 + bb * KOUT + t] = sc;
    }
}

extern "C" void kernel_launch(void* const* d_in, const int* in_sizes, int n_in,
                              void* d_out, int out_size) {
    const float* lafs   = (const float*)d_in[0];
    const float* scores = (const float*)d_in[1];
    float* out = (float*)d_out;

    cudaFuncSetAttribute(sortmerge_kernel, cudaFuncAttributeMaxDynamicSharedMemorySize, 65536);

    scatter_nms_kernel<<<128, 256>>>(lafs, scores);
    sortmerge_kernel<<<32, 1024, 65536>>>(lafs, out);
}